// round 6
// baseline (speedup 1.0000x reference)
#include <cuda_runtime.h>
#include <cstdint>

#define T_STEPS 200

typedef unsigned long long u64t;

// ---------------- scratch (device globals: allocation-free) ----------------
// g_p layout: [t][k/4][b][4]  (k = (h*64+c)*9+pos, 1152 total; 288 k4-groups)
__device__ float g_p[(size_t)T_STEPS * 288 * 64 * 4];   // ~59MB
// spike MASKS (uint16 slice per (b, og)); replaces float spike arrays
__device__ unsigned short g_m3[3 * 64 * 16];   // [slot][b][og]   conv3 spikes
__device__ unsigned short g_mr[2 * 64 * 16];   // [buf][b][og]    recurrent spikes
__device__ unsigned short g_msf[2 * 64 * 8];   // [buf][b][og<8]  fc1 spikes
// per-bg-group barriers (padded to separate cache lines)
__device__ unsigned g_cnt[4 * 32];
__device__ volatile unsigned g_gen[4 * 32];

__device__ __forceinline__ void gridbar_g(int grp, unsigned n) {
    __syncthreads();
    if (threadIdx.x == 0) {
        unsigned* cnt = &g_cnt[grp * 32];
        volatile unsigned* gen = &g_gen[grp * 32];
        unsigned g = *gen;
        __threadfence();
        if (atomicAdd(cnt, 1u) == n - 1u) {
            *cnt = 0;
            __threadfence();
            *gen = g + 1u;
        } else {
            while (*gen == g) { }
        }
        __threadfence();
    }
    __syncthreads();
}

// ---- packed f32x2 helpers (each lane = independent rn op: bit-exact) ----
__device__ __forceinline__ u64t pk2(float lo, float hi) {
    u64t r; asm("mov.b64 %0, {%1, %2};" : "=l"(r) : "f"(lo), "f"(hi)); return r;
}
__device__ __forceinline__ void upk2(u64t v, float& lo, float& hi) {
    asm("mov.b64 {%0, %1}, %2;" : "=f"(lo), "=f"(hi) : "l"(v));
}
__device__ __forceinline__ u64t fma2(u64t a, u64t b, u64t c) {
    u64t d; asm("fma.rn.f32x2 %0, %1, %2, %3;" : "=l"(d) : "l"(a), "l"(b), "l"(c));
    return d;
}

// LIF update, unfused rounding (XLA elementwise semantics)
__device__ __forceinline__ void lif_update(float psp, float& cur, float& volt, float& spk) {
    cur  = __fadd_rn(__fmul_rn(0.5f, cur), psp);
    volt = __fadd_rn(__fmul_rn(__fmul_rn(0.75f, volt), __fadd_rn(1.f, -spk)), cur);
    spk  = (volt > 0.5f) ? 1.f : 0.f;
}

// ============================================================================
// Phase A: conv1 -> LIF -> conv2 (FFMA2 oc-pairs) -> LIF -> avgpool. (as R5)
// ============================================================================
#define A_XS    0
#define A_W1S   100
#define A_B1S   676
#define A_B2S   740
#define A_S1S   804
#define A_S2S   4964
#define A_W2P   7268
#define A_TOT   44132

__global__ __launch_bounds__(128, 1)
void phaseA_kernel(const float* __restrict__ input,
                   const float* __restrict__ w1, const float* __restrict__ b1,
                   const float* __restrict__ w2, const float* __restrict__ b2)
{
    extern __shared__ float sm[];
    float* xs  = sm + A_XS;
    float* w1s = sm + A_W1S;
    float* b1s = sm + A_B1S;
    float* b2s = sm + A_B2S;
    float* s1s = sm + A_S1S;
    float* s2s = sm + A_S2S;
    float* w2p = sm + A_W2P;

    const int tid = threadIdx.x;
    const int b   = blockIdx.x >> 1;
    const int h   = blockIdx.x & 1;

    for (int i = tid; i < 36864; i += 128) {
        int oc = i / 576;
        int r  = i - oc * 576;
        w2p[(r * 32 + (oc >> 1)) * 2 + (oc & 1)] = w2[h * 36864 + i];
    }
    for (int i = tid; i < 576; i += 128) w1s[i] = w1[i];
    if (tid < 64) { b1s[tid] = b1[tid]; b2s[tid] = b2[h * 64 + tid]; }
    for (int i = tid; i < 4160; i += 128) s1s[i] = 0.f;
    for (int i = tid; i < 2304; i += 128) s2s[i] = 0.f;
    __syncthreads();

    const int p = tid >> 2;
    const int q = tid & 3;
    const int qy = q >> 1, qx = q & 1;
    const int y0a = qy * 4, x0a = qx * 4;
    const int y0b = qy * 3, x0b = qx * 3;

    float c1[2][16], v1[2][16];
    float c2[2][9], v2[2][9], sp2[2][9];
#pragma unroll
    for (int o = 0; o < 2; ++o) {
#pragma unroll
        for (int i = 0; i < 16; ++i) { c1[o][i] = 0.f; v1[o][i] = 0.f; }
#pragma unroll
        for (int i = 0; i < 9; ++i) { c2[o][i] = 0.f; v2[o][i] = 0.f; sp2[o][i] = 0.f; }
    }

    const float* xin = input + (size_t)b * 20000;

    for (int t = 0; t < T_STEPS; ++t) {
        if (tid < 100) xs[tid] = xin[tid * 200 + t];
        __syncthreads();

#pragma unroll
        for (int o = 0; o < 2; ++o) {
            const int occ = 2 * p + o;
            const float bb = b1s[occ];
            const float* wv = w1s + occ * 9;
#pragma unroll
            for (int iy = 0; iy < 4; ++iy) {
#pragma unroll
                for (int ix = 0; ix < 4; ++ix) {
                    const int y = y0a + iy, x = x0a + ix;
                    float a = 0.f;
#pragma unroll
                    for (int ky = 0; ky < 3; ++ky)
#pragma unroll
                        for (int kx = 0; kx < 3; ++kx)
                            a = __fmaf_rn(xs[(y + ky) * 10 + (x + kx)], wv[ky * 3 + kx], a);
                    const float psp = __fadd_rn(a, bb);
                    const int i = iy * 4 + ix;
                    const int sidx = occ * 65 + y * 8 + x;
                    float sp = s1s[sidx];
                    lif_update(psp, c1[o][i], v1[o][i], sp);
                    s1s[sidx] = sp;
                }
            }
        }
        __syncthreads();

        {
            u64t acc[9];
#pragma unroll
            for (int j = 0; j < 9; ++j) acc[j] = 0ull;

#pragma unroll 2
            for (int ic = 0; ic < 64; ++ic) {
                u64t ins[5][5];
#pragma unroll
                for (int r = 0; r < 5; ++r)
#pragma unroll
                    for (int c = 0; c < 5; ++c) {
                        float v = s1s[ic * 65 + (y0b + r) * 8 + (x0b + c)];
                        ins[r][c] = pk2(v, v);
                    }
#pragma unroll
                for (int kk = 0; kk < 9; ++kk) {
                    const int ky = kk / 3, kx = kk % 3;
                    const u64t w = *(const u64t*)(w2p + ((ic * 9 + kk) * 32 + p) * 2);
#pragma unroll
                    for (int dy = 0; dy < 3; ++dy)
#pragma unroll
                        for (int dx = 0; dx < 3; ++dx)
                            acc[dy * 3 + dx] = fma2(ins[dy + ky][dx + kx], w,
                                                    acc[dy * 3 + dx]);
                }
            }

#pragma unroll
            for (int j = 0; j < 9; ++j) {
                const int dy = j / 3, dx = j % 3;
                float alo, ahi;
                upk2(acc[j], alo, ahi);
#pragma unroll
                for (int o = 0; o < 2; ++o) {
                    const int occ = 2 * p + o;
                    const float a = o ? ahi : alo;
                    const float psp = __fadd_rn(a, b2s[occ]);
                    lif_update(psp, c2[o][j], v2[o][j], sp2[o][j]);
                    s2s[occ * 36 + (y0b + dy) * 6 + (x0b + dx)] = sp2[o][j];
                }
            }
        }
        __syncthreads();

        for (int idx = tid; idx < 576; idx += 128) {
            int c = idx / 9;
            int pos = idx - c * 9;
            int py = pos / 3, px = pos - py * 3;
            float v = 0.25f * ((s2s[c * 36 + (2 * py) * 6 + 2 * px]
                              + s2s[c * 36 + (2 * py) * 6 + 2 * px + 1])
                             + (s2s[c * 36 + (2 * py + 1) * 6 + 2 * px]
                              + s2s[c * 36 + (2 * py + 1) * 6 + 2 * px + 1]));
            int k = (h * 64 + c) * 9 + pos;
            g_p[(size_t)t * 73728 + (size_t)(k >> 2) * 256 + b * 4 + (k & 3)] = v;
        }
    }
}

// ============================================================================
// Phase B: conv3 dense + sparse mask-driven tc/rec/fc1/fc2.
// grid = 64 CTAs (16 og x 4 bg), 256 threads. 2 grid barriers per step.
// ============================================================================
#define B_W3S   0        // 16*1160 = 18560
#define B_TCW   18560    // 12672
#define B_RECW  31232    // 4224
#define B_F1W   35456    // 4224
#define B_B3    39680    // 16
#define B_TCB   39696    // 48
#define B_RECB  39744    // 16
#define B_F1B   39760    // 16
#define B_F2S   39776    // 256
#define B_TSW   40032    // 200
#define B_PBUF  40232    // 2*2048 = 4096 (conv3 chunk double buffer; pb1 reused for spikes)
#define B_TOT   44328    // floats -> 177312 bytes

__global__ __launch_bounds__(256, 1)
void phaseB_kernel(const float* __restrict__ w3, const float* __restrict__ b3,
                   const float* __restrict__ tcw, const float* __restrict__ tcb,
                   const float* __restrict__ recw, const float* __restrict__ recb,
                   const float* __restrict__ f1w, const float* __restrict__ f1b,
                   const float* __restrict__ f2w, const float* __restrict__ tsw,
                   float* __restrict__ out)
{
    extern __shared__ float sm[];
    float* w3s   = sm + B_W3S;
    float* tcws  = sm + B_TCW;
    float* recws = sm + B_RECW;
    float* f1ws  = sm + B_F1W;
    float* b3s   = sm + B_B3;
    float* tcbs  = sm + B_TCB;
    float* recbs = sm + B_RECB;
    float* f1bs  = sm + B_F1B;
    float* f2s   = sm + B_F2S;
    float* tsws  = sm + B_TSW;
    float* pb0   = sm + B_PBUF;
    float* pb1   = sm + B_PBUF + 2048;

    const int tid = threadIdx.x;
    const int og = blockIdx.x >> 2;   // 0..15
    const int bg = blockIdx.x & 3;    // 0..3 (independent barrier group)
    const int ol = tid >> 4;          // 0..15
    const int bl = tid & 15;          // 0..15
    const int oc = og * 16 + ol;
    const int b  = bg * 16 + bl;
    (void)oc;

    // ---- one-time weight staging ----
    for (int g = tid; g < 16 * 1152; g += 256) {
        int o = g / 1152, k = g - o * 1152;
        w3s[o * 1160 + k] = w3[(size_t)(og * 16 + o) * 1152 + k];
    }
    for (int g = tid; g < 3 * 16 * 256; g += 256) {
        int i = g >> 12, r = g & 4095, o = r >> 8, k = r & 255;
        tcws[(i * 16 + o) * 264 + k] = tcw[i * 65536 + (og * 16 + o) * 256 + k];
    }
    for (int g = tid; g < 4096; g += 256) {
        int o = g >> 8, k = g & 255;
        recws[o * 264 + k] = recw[(og * 16 + o) * 256 + k];
        if (og < 8) f1ws[o * 264 + k] = f1w[(og * 16 + o) * 256 + k];
    }
    if (tid < 16) {
        b3s[tid] = b3[og * 16 + tid];
        recbs[tid] = recb[og * 16 + tid];
        if (og < 8) f1bs[tid] = f1b[og * 16 + tid];
    }
    if (tid < 48) tcbs[tid] = tcb[(tid >> 4) * 256 + og * 16 + (tid & 15)];
    f2s[tid] = f2w[tid];
    for (int g = tid; g < 200; g += 256) tsws[g] = tsw[g];
    __syncthreads();

    float cur3 = 0.f, volt3 = 0.f, spk3 = 0.f;
    float curt = 0.f, voltt = 0.f, spkt = 0.f;
    float curr = 0.f, voltr = 0.f, spkr = 0.f;
    float curf = 0.f, voltf = 0.f, spkf = 0.f;
    float outacc = 0.f;

    // conv3 staging indices: 512 float4/chunk, 2 per thread
    const int k4a = tid >> 4;          // 0..15
    const int k4b = 16 + (tid >> 4);   // 16..31
    const int bls = tid & 15;

    for (int t = 0; t < T_STEPS; ++t) {
        // ========== conv3: SMEM double-buffered chunks + serial FMA chain ==========
        {
            const float* tbase = g_p + (size_t)t * 73728 + bg * 64;
            float4 r0 = *(const float4*)(tbase + (size_t)(k4a) * 256 + bls * 4);
            float4 r1 = *(const float4*)(tbase + (size_t)(k4b) * 256 + bls * 4);
            *(float4*)(pb0 + (k4a * 16 + bls) * 4) = r0;
            *(float4*)(pb0 + (k4b * 16 + bls) * 4) = r1;
            __syncthreads();

            float a = 0.f;
            const float* wr = w3s + ol * 1160;
            for (int c = 0; c < 9; ++c) {
                float* cb = (c & 1) ? pb1 : pb0;
                float* nb = (c & 1) ? pb0 : pb1;
                float4 n0, n1;
                if (c < 8) {
                    n0 = *(const float4*)(tbase + (size_t)((c + 1) * 32 + k4a) * 256 + bls * 4);
                    n1 = *(const float4*)(tbase + (size_t)((c + 1) * 32 + k4b) * 256 + bls * 4);
                }
#pragma unroll
                for (int k4 = 0; k4 < 32; ++k4) {
                    float4 w = *(const float4*)(wr + (c * 32 + k4) * 4);
                    float4 x = *(const float4*)(cb + (k4 * 16 + bl) * 4);
                    a = __fmaf_rn(w.x, x.x, a);
                    a = __fmaf_rn(w.y, x.y, a);
                    a = __fmaf_rn(w.z, x.z, a);
                    a = __fmaf_rn(w.w, x.w, a);
                }
                if (c < 8) {
                    *(float4*)(nb + (k4a * 16 + bls) * 4) = n0;
                    *(float4*)(nb + (k4b * 16 + bls) * 4) = n1;
                }
                __syncthreads();
            }

            const float psp = __fadd_rn(a, b3s[ol]);
            lif_update(psp, cur3, volt3, spk3);
        }
        // stage spikes, build + publish 16-bit mask slice (pb1 is free here)
        pb1[tid] = spk3;
        __syncthreads();
        if (tid < 16) {
            unsigned m = 0;
#pragma unroll
            for (int o = 0; o < 16; ++o)
                m |= (pb1[o * 16 + tid] > 0.5f ? 1u : 0u) << o;
            g_m3[(((t % 3) * 64) + bg * 16 + tid) * 16 + og] = (unsigned short)m;
        }
        gridbar_g(bg, 16);   // -------- bar 1 --------

        // ========== fc2 for step t-1 (og<2, ol==0) ==========
        if (og < 2 && ol == 0 && t >= 1) {
            const uint4 mv = *(const uint4*)&g_msf[((((t - 1) & 1) * 64) + b) * 8];
            unsigned M4[4] = {mv.x, mv.y, mv.z, mv.w};
            const float* rp0 = f2s + og * 128;
            float d = 0.f, pend = 0.f; int havep = 0;
#pragma unroll
            for (int w = 0; w < 4; ++w) {
                unsigned m = M4[w];
                const float* rp = rp0 + w * 32;
                while (m) {
                    int i = __ffs(m) - 1; m &= m - 1;
                    float nv = rp[i];
                    if (havep) d = __fadd_rn(d, pend);
                    pend = nv; havep = 1;
                }
            }
            if (havep) d = __fadd_rn(d, pend);
            outacc = __fadd_rn(outacc, __fmul_rn(d, tsws[t - 1]));
        }

        // ========== tc (3 taps) + rec: combined sparse 4-chain loop ==========
        {
            unsigned a0[8], a1[8], a2[8], ar[8];
            {
                const uint4* p0 = (const uint4*)&g_m3[(((t % 3) * 64) + b) * 16];
                uint4 u = p0[0], v = p0[1];
                a0[0]=u.x; a0[1]=u.y; a0[2]=u.z; a0[3]=u.w;
                a0[4]=v.x; a0[5]=v.y; a0[6]=v.z; a0[7]=v.w;
            }
            if (t >= 1) {
                const uint4* p1 = (const uint4*)&g_m3[((((t + 2) % 3) * 64) + b) * 16];
                uint4 u = p1[0], v = p1[1];
                a1[0]=u.x; a1[1]=u.y; a1[2]=u.z; a1[3]=u.w;
                a1[4]=v.x; a1[5]=v.y; a1[6]=v.z; a1[7]=v.w;
            } else {
#pragma unroll
                for (int w = 0; w < 8; ++w) a1[w] = 0u;
            }
            if (t >= 2) {
                const uint4* p2 = (const uint4*)&g_m3[((((t + 1) % 3) * 64) + b) * 16];
                uint4 u = p2[0], v = p2[1];
                a2[0]=u.x; a2[1]=u.y; a2[2]=u.z; a2[3]=u.w;
                a2[4]=v.x; a2[5]=v.y; a2[6]=v.z; a2[7]=v.w;
            } else {
#pragma unroll
                for (int w = 0; w < 8; ++w) a2[w] = 0u;
            }
            if (t >= 1) {
                const uint4* pr = (const uint4*)&g_mr[((((t & 1) ^ 1) * 64) + b) * 16];
                uint4 u = pr[0], v = pr[1];
                ar[0]=u.x; ar[1]=u.y; ar[2]=u.z; ar[3]=u.w;
                ar[4]=v.x; ar[5]=v.y; ar[6]=v.z; ar[7]=v.w;
            } else {
#pragma unroll
                for (int w = 0; w < 8; ++w) ar[w] = 0u;
            }

            const float* r0 = tcws + (0 * 16 + ol) * 264;
            const float* r1 = tcws + (1 * 16 + ol) * 264;
            const float* r2 = tcws + (2 * 16 + ol) * 264;
            const float* rr = recws + ol * 264;

            float d0 = 0.f, d1 = 0.f, d2 = 0.f, dr = 0.f;
#pragma unroll
            for (int w = 0; w < 8; ++w) {
                unsigned m0 = a0[w], m1 = a1[w], m2 = a2[w], mrr = ar[w];
                const float* q0 = r0 + w * 32;
                const float* q1 = r1 + w * 32;
                const float* q2 = r2 + w * 32;
                const float* qr = rr + w * 32;
                while (m0 | m1 | m2 | mrr) {
                    if (m0) { int i = __ffs(m0) - 1; m0 &= m0 - 1; d0 = __fadd_rn(d0, q0[i]); }
                    if (m1) { int i = __ffs(m1) - 1; m1 &= m1 - 1; d1 = __fadd_rn(d1, q1[i]); }
                    if (m2) { int i = __ffs(m2) - 1; m2 &= m2 - 1; d2 = __fadd_rn(d2, q2[i]); }
                    if (mrr){ int i = __ffs(mrr) - 1; mrr &= mrr - 1; dr = __fadd_rn(dr, qr[i]); }
                }
            }

            float a = 0.f;
            a = __fadd_rn(a, __fadd_rn(d0, tcbs[0 * 16 + ol]));
            if (t >= 1) a = __fadd_rn(a, __fadd_rn(d1, tcbs[1 * 16 + ol]));
            if (t >= 2) a = __fadd_rn(a, __fadd_rn(d2, tcbs[2 * 16 + ol]));
            lif_update(a, curt, voltt, spkt);

            const float pr = __fadd_rn(__fadd_rn(spkt, dr), recbs[ol]);
            lif_update(pr, curr, voltr, spkr);
        }
        // publish recurrent spike masks
        pb1[tid] = spkr;
        __syncthreads();
        if (tid < 16) {
            unsigned m = 0;
#pragma unroll
            for (int o = 0; o < 16; ++o)
                m |= (pb1[o * 16 + tid] > 0.5f ? 1u : 0u) << o;
            g_mr[(((t & 1) * 64) + bg * 16 + tid) * 16 + og] = (unsigned short)m;
        }
        gridbar_g(bg, 16);   // -------- bar 2 --------

        // ========== fc1 + LIF (og < 8), sparse pipelined chain ==========
        if (og < 8) {
            unsigned M8[8];
            {
                const uint4* p = (const uint4*)&g_mr[(((t & 1) * 64) + b) * 16];
                uint4 u = p[0], v = p[1];
                M8[0]=u.x; M8[1]=u.y; M8[2]=u.z; M8[3]=u.w;
                M8[4]=v.x; M8[5]=v.y; M8[6]=v.z; M8[7]=v.w;
            }
            const float* row = f1ws + ol * 264;
            float d = 0.f, pend = 0.f; int havep = 0;
#pragma unroll
            for (int w = 0; w < 8; ++w) {
                unsigned m = M8[w];
                const float* rp = row + w * 32;
                while (m) {
                    int i = __ffs(m) - 1; m &= m - 1;
                    float nv = rp[i];
                    if (havep) d = __fadd_rn(d, pend);
                    pend = nv; havep = 1;
                }
            }
            if (havep) d = __fadd_rn(d, pend);
            const float psp = __fadd_rn(d, f1bs[ol]);
            lif_update(psp, curf, voltf, spkf);
            pb1[tid] = spkf;
        }
        __syncthreads();
        if (og < 8 && tid < 16) {
            unsigned m = 0;
#pragma unroll
            for (int o = 0; o < 16; ++o)
                m |= (pb1[o * 16 + tid] > 0.5f ? 1u : 0u) << o;
            g_msf[(((t & 1) * 64) + bg * 16 + tid) * 8 + og] = (unsigned short)m;
        }
        // (no bar 3: fc2(t) runs after bar1 of step t+1, which orders fc1 writes)
    }

    gridbar_g(bg, 16);   // final: order fc1(199) mask writes
    if (og < 2 && ol == 0) {
        const uint4 mv = *(const uint4*)&g_msf[((((T_STEPS - 1) & 1) * 64) + b) * 8];
        unsigned M4[4] = {mv.x, mv.y, mv.z, mv.w};
        const float* rp0 = f2s + og * 128;
        float d = 0.f, pend = 0.f; int havep = 0;
#pragma unroll
        for (int w = 0; w < 4; ++w) {
            unsigned m = M4[w];
            const float* rp = rp0 + w * 32;
            while (m) {
                int i = __ffs(m) - 1; m &= m - 1;
                float nv = rp[i];
                if (havep) d = __fadd_rn(d, pend);
                pend = nv; havep = 1;
            }
        }
        if (havep) d = __fadd_rn(d, pend);
        outacc = __fadd_rn(outacc, __fmul_rn(d, tsws[T_STEPS - 1]));
        out[b * 2 + og] = outacc;
    }
}

// ============================================================================
extern "C" void kernel_launch(void* const* d_in, const int* in_sizes, int n_in,
                              void* d_out, int out_size)
{
    (void)in_sizes; (void)n_in; (void)out_size;
    const float* input = (const float*)d_in[0];
    const float* w1   = (const float*)d_in[1];
    const float* b1   = (const float*)d_in[2];
    const float* w2   = (const float*)d_in[3];
    const float* b2   = (const float*)d_in[4];
    const float* w3   = (const float*)d_in[5];
    const float* b3   = (const float*)d_in[6];
    const float* tcw  = (const float*)d_in[7];
    const float* tcb  = (const float*)d_in[8];
    const float* recw = (const float*)d_in[9];
    const float* recb = (const float*)d_in[10];
    const float* f1w  = (const float*)d_in[11];
    const float* f1b  = (const float*)d_in[12];
    const float* f2w  = (const float*)d_in[13];
    const float* tsw  = (const float*)d_in[14];
    float* out = (float*)d_out;

    cudaFuncSetAttribute(phaseA_kernel, cudaFuncAttributeMaxDynamicSharedMemorySize,
                         A_TOT * sizeof(float));
    cudaFuncSetAttribute(phaseB_kernel, cudaFuncAttributeMaxDynamicSharedMemorySize,
                         B_TOT * sizeof(float));

    phaseA_kernel<<<128, 128, A_TOT * sizeof(float)>>>(input, w1, b1, w2, b2);
    phaseB_kernel<<<64, 256, B_TOT * sizeof(float)>>>(w3, b3, tcw, tcb, recw, recb,
                                                      f1w, f1b, f2w, tsw, out);
}

// round 7
// speedup vs baseline: 1.0016x; 1.0016x over previous
#include <cuda_runtime.h>
#include <cstdint>

#define T_STEPS 200

typedef unsigned long long u64t;

// ---------------- scratch (device globals: allocation-free) ----------------
// g_p layout: [t][k/4][b][4]  (k = (h*64+c)*9+pos, 1152 total; 288 k4-groups)
__device__ float g_p[(size_t)T_STEPS * 288 * 64 * 4];   // ~59MB
// spike MASKS (uint16 slice per (b, og)); replaces float spike arrays
__device__ unsigned short g_m3[3 * 64 * 16];   // [slot][b][og]   conv3 spikes
__device__ unsigned short g_mr[2 * 64 * 16];   // [buf][b][og]    recurrent spikes
__device__ unsigned short g_msf[2 * 64 * 8];   // [buf][b][og<8]  fc1 spikes
// per-bg-group barriers (padded to separate cache lines)
__device__ unsigned g_cnt[4 * 32];
__device__ volatile unsigned g_gen[4 * 32];

__device__ __forceinline__ void gridbar_g(int grp, unsigned n) {
    __syncthreads();
    if (threadIdx.x == 0) {
        unsigned* cnt = &g_cnt[grp * 32];
        volatile unsigned* gen = &g_gen[grp * 32];
        unsigned g = *gen;
        __threadfence();
        if (atomicAdd(cnt, 1u) == n - 1u) {
            *cnt = 0;
            __threadfence();
            *gen = g + 1u;
        } else {
            while (*gen == g) { }
        }
        __threadfence();
    }
    __syncthreads();
}

// ---- packed f32x2 helpers (each lane = independent rn op: bit-exact) ----
__device__ __forceinline__ u64t pk2(float lo, float hi) {
    u64t r; asm("mov.b64 %0, {%1, %2};" : "=l"(r) : "f"(lo), "f"(hi)); return r;
}
__device__ __forceinline__ void upk2(u64t v, float& lo, float& hi) {
    asm("mov.b64 {%0, %1}, %2;" : "=f"(lo), "=f"(hi) : "l"(v));
}
__device__ __forceinline__ u64t fma2(u64t a, u64t b, u64t c) {
    u64t d; asm("fma.rn.f32x2 %0, %1, %2, %3;" : "=l"(d) : "l"(a), "l"(b), "l"(c));
    return d;
}

// LIF update, unfused rounding (XLA elementwise semantics)
__device__ __forceinline__ void lif_update(float psp, float& cur, float& volt, float& spk) {
    cur  = __fadd_rn(__fmul_rn(0.5f, cur), psp);
    volt = __fadd_rn(__fmul_rn(__fmul_rn(0.75f, volt), __fadd_rn(1.f, -spk)), cur);
    spk  = (volt > 0.5f) ? 1.f : 0.f;
}

// ============================================================================
// Phase A: conv1 -> LIF -> conv2 (FFMA2 oc-pairs) -> LIF -> avgpool. (as R5)
// ============================================================================
#define A_XS    0
#define A_W1S   100
#define A_B1S   676
#define A_B2S   740
#define A_S1S   804
#define A_S2S   4964
#define A_W2P   7268
#define A_TOT   44132

__global__ __launch_bounds__(128, 1)
void phaseA_kernel(const float* __restrict__ input,
                   const float* __restrict__ w1, const float* __restrict__ b1,
                   const float* __restrict__ w2, const float* __restrict__ b2)
{
    extern __shared__ float sm[];
    float* xs  = sm + A_XS;
    float* w1s = sm + A_W1S;
    float* b1s = sm + A_B1S;
    float* b2s = sm + A_B2S;
    float* s1s = sm + A_S1S;
    float* s2s = sm + A_S2S;
    float* w2p = sm + A_W2P;

    const int tid = threadIdx.x;
    const int b   = blockIdx.x >> 1;
    const int h   = blockIdx.x & 1;

    for (int i = tid; i < 36864; i += 128) {
        int oc = i / 576;
        int r  = i - oc * 576;
        w2p[(r * 32 + (oc >> 1)) * 2 + (oc & 1)] = w2[h * 36864 + i];
    }
    for (int i = tid; i < 576; i += 128) w1s[i] = w1[i];
    if (tid < 64) { b1s[tid] = b1[tid]; b2s[tid] = b2[h * 64 + tid]; }
    for (int i = tid; i < 4160; i += 128) s1s[i] = 0.f;
    for (int i = tid; i < 2304; i += 128) s2s[i] = 0.f;
    __syncthreads();

    const int p = tid >> 2;
    const int q = tid & 3;
    const int qy = q >> 1, qx = q & 1;
    const int y0a = qy * 4, x0a = qx * 4;
    const int y0b = qy * 3, x0b = qx * 3;

    float c1[2][16], v1[2][16];
    float c2[2][9], v2[2][9], sp2[2][9];
#pragma unroll
    for (int o = 0; o < 2; ++o) {
#pragma unroll
        for (int i = 0; i < 16; ++i) { c1[o][i] = 0.f; v1[o][i] = 0.f; }
#pragma unroll
        for (int i = 0; i < 9; ++i) { c2[o][i] = 0.f; v2[o][i] = 0.f; sp2[o][i] = 0.f; }
    }

    const float* xin = input + (size_t)b * 20000;

    for (int t = 0; t < T_STEPS; ++t) {
        if (tid < 100) xs[tid] = xin[tid * 200 + t];
        __syncthreads();

#pragma unroll
        for (int o = 0; o < 2; ++o) {
            const int occ = 2 * p + o;
            const float bb = b1s[occ];
            const float* wv = w1s + occ * 9;
#pragma unroll
            for (int iy = 0; iy < 4; ++iy) {
#pragma unroll
                for (int ix = 0; ix < 4; ++ix) {
                    const int y = y0a + iy, x = x0a + ix;
                    float a = 0.f;
#pragma unroll
                    for (int ky = 0; ky < 3; ++ky)
#pragma unroll
                        for (int kx = 0; kx < 3; ++kx)
                            a = __fmaf_rn(xs[(y + ky) * 10 + (x + kx)], wv[ky * 3 + kx], a);
                    const float psp = __fadd_rn(a, bb);
                    const int i = iy * 4 + ix;
                    const int sidx = occ * 65 + y * 8 + x;
                    float sp = s1s[sidx];
                    lif_update(psp, c1[o][i], v1[o][i], sp);
                    s1s[sidx] = sp;
                }
            }
        }
        __syncthreads();

        {
            u64t acc[9];
#pragma unroll
            for (int j = 0; j < 9; ++j) acc[j] = 0ull;

#pragma unroll 2
            for (int ic = 0; ic < 64; ++ic) {
                u64t ins[5][5];
#pragma unroll
                for (int r = 0; r < 5; ++r)
#pragma unroll
                    for (int c = 0; c < 5; ++c) {
                        float v = s1s[ic * 65 + (y0b + r) * 8 + (x0b + c)];
                        ins[r][c] = pk2(v, v);
                    }
#pragma unroll
                for (int kk = 0; kk < 9; ++kk) {
                    const int ky = kk / 3, kx = kk % 3;
                    const u64t w = *(const u64t*)(w2p + ((ic * 9 + kk) * 32 + p) * 2);
#pragma unroll
                    for (int dy = 0; dy < 3; ++dy)
#pragma unroll
                        for (int dx = 0; dx < 3; ++dx)
                            acc[dy * 3 + dx] = fma2(ins[dy + ky][dx + kx], w,
                                                    acc[dy * 3 + dx]);
                }
            }

#pragma unroll
            for (int j = 0; j < 9; ++j) {
                const int dy = j / 3, dx = j % 3;
                float alo, ahi;
                upk2(acc[j], alo, ahi);
#pragma unroll
                for (int o = 0; o < 2; ++o) {
                    const int occ = 2 * p + o;
                    const float a = o ? ahi : alo;
                    const float psp = __fadd_rn(a, b2s[occ]);
                    lif_update(psp, c2[o][j], v2[o][j], sp2[o][j]);
                    s2s[occ * 36 + (y0b + dy) * 6 + (x0b + dx)] = sp2[o][j];
                }
            }
        }
        __syncthreads();

        for (int idx = tid; idx < 576; idx += 128) {
            int c = idx / 9;
            int pos = idx - c * 9;
            int py = pos / 3, px = pos - py * 3;
            float v = 0.25f * ((s2s[c * 36 + (2 * py) * 6 + 2 * px]
                              + s2s[c * 36 + (2 * py) * 6 + 2 * px + 1])
                             + (s2s[c * 36 + (2 * py + 1) * 6 + 2 * px]
                              + s2s[c * 36 + (2 * py + 1) * 6 + 2 * px + 1]));
            int k = (h * 64 + c) * 9 + pos;
            g_p[(size_t)t * 73728 + (size_t)(k >> 2) * 256 + b * 4 + (k & 3)] = v;
        }
    }
}

// ============================================================================
// Phase B: conv3 dense + sparse mask-driven tc/rec/fc1/fc2.
// grid = 64 CTAs (16 og x 4 bg), 256 threads. 2 grid barriers per step.
// ============================================================================
#define B_W3S   0        // 16*1160 = 18560
#define B_TCW   18560    // 12672
#define B_RECW  31232    // 4224
#define B_F1W   35456    // 4224
#define B_B3    39680    // 16
#define B_TCB   39696    // 48
#define B_RECB  39744    // 16
#define B_F1B   39760    // 16
#define B_F2S   39776    // 256
#define B_TSW   40032    // 200
#define B_PBUF  40232    // 2*2048 = 4096 (conv3 chunk double buffer; pb1 reused for spikes)
#define B_TOT   44328    // floats -> 177312 bytes

__global__ __launch_bounds__(256, 1)
void phaseB_kernel(const float* __restrict__ w3, const float* __restrict__ b3,
                   const float* __restrict__ tcw, const float* __restrict__ tcb,
                   const float* __restrict__ recw, const float* __restrict__ recb,
                   const float* __restrict__ f1w, const float* __restrict__ f1b,
                   const float* __restrict__ f2w, const float* __restrict__ tsw,
                   float* __restrict__ out)
{
    extern __shared__ float sm[];
    float* w3s   = sm + B_W3S;
    float* tcws  = sm + B_TCW;
    float* recws = sm + B_RECW;
    float* f1ws  = sm + B_F1W;
    float* b3s   = sm + B_B3;
    float* tcbs  = sm + B_TCB;
    float* recbs = sm + B_RECB;
    float* f1bs  = sm + B_F1B;
    float* f2s   = sm + B_F2S;
    float* tsws  = sm + B_TSW;
    float* pb0   = sm + B_PBUF;
    float* pb1   = sm + B_PBUF + 2048;

    const int tid = threadIdx.x;
    const int og = blockIdx.x >> 2;   // 0..15
    const int bg = blockIdx.x & 3;    // 0..3 (independent barrier group)
    const int ol = tid >> 4;          // 0..15
    const int bl = tid & 15;          // 0..15
    const int oc = og * 16 + ol;
    const int b  = bg * 16 + bl;
    (void)oc;

    // ---- one-time weight staging ----
    for (int g = tid; g < 16 * 1152; g += 256) {
        int o = g / 1152, k = g - o * 1152;
        w3s[o * 1160 + k] = w3[(size_t)(og * 16 + o) * 1152 + k];
    }
    for (int g = tid; g < 3 * 16 * 256; g += 256) {
        int i = g >> 12, r = g & 4095, o = r >> 8, k = r & 255;
        tcws[(i * 16 + o) * 264 + k] = tcw[i * 65536 + (og * 16 + o) * 256 + k];
    }
    for (int g = tid; g < 4096; g += 256) {
        int o = g >> 8, k = g & 255;
        recws[o * 264 + k] = recw[(og * 16 + o) * 256 + k];
        if (og < 8) f1ws[o * 264 + k] = f1w[(og * 16 + o) * 256 + k];
    }
    if (tid < 16) {
        b3s[tid] = b3[og * 16 + tid];
        recbs[tid] = recb[og * 16 + tid];
        if (og < 8) f1bs[tid] = f1b[og * 16 + tid];
    }
    if (tid < 48) tcbs[tid] = tcb[(tid >> 4) * 256 + og * 16 + (tid & 15)];
    f2s[tid] = f2w[tid];
    for (int g = tid; g < 200; g += 256) tsws[g] = tsw[g];
    __syncthreads();

    float cur3 = 0.f, volt3 = 0.f, spk3 = 0.f;
    float curt = 0.f, voltt = 0.f, spkt = 0.f;
    float curr = 0.f, voltr = 0.f, spkr = 0.f;
    float curf = 0.f, voltf = 0.f, spkf = 0.f;
    float outacc = 0.f;

    // conv3 staging indices: 512 float4/chunk, 2 per thread
    const int k4a = tid >> 4;          // 0..15
    const int k4b = 16 + (tid >> 4);   // 16..31
    const int bls = tid & 15;

    for (int t = 0; t < T_STEPS; ++t) {
        // ========== conv3: SMEM double-buffered chunks + serial FMA chain ==========
        {
            const float* tbase = g_p + (size_t)t * 73728 + bg * 64;
            float4 r0 = *(const float4*)(tbase + (size_t)(k4a) * 256 + bls * 4);
            float4 r1 = *(const float4*)(tbase + (size_t)(k4b) * 256 + bls * 4);
            *(float4*)(pb0 + (k4a * 16 + bls) * 4) = r0;
            *(float4*)(pb0 + (k4b * 16 + bls) * 4) = r1;
            __syncthreads();

            float a = 0.f;
            const float* wr = w3s + ol * 1160;
            for (int c = 0; c < 9; ++c) {
                float* cb = (c & 1) ? pb1 : pb0;
                float* nb = (c & 1) ? pb0 : pb1;
                float4 n0, n1;
                if (c < 8) {
                    n0 = *(const float4*)(tbase + (size_t)((c + 1) * 32 + k4a) * 256 + bls * 4);
                    n1 = *(const float4*)(tbase + (size_t)((c + 1) * 32 + k4b) * 256 + bls * 4);
                }
#pragma unroll
                for (int k4 = 0; k4 < 32; ++k4) {
                    float4 w = *(const float4*)(wr + (c * 32 + k4) * 4);
                    float4 x = *(const float4*)(cb + (k4 * 16 + bl) * 4);
                    a = __fmaf_rn(w.x, x.x, a);
                    a = __fmaf_rn(w.y, x.y, a);
                    a = __fmaf_rn(w.z, x.z, a);
                    a = __fmaf_rn(w.w, x.w, a);
                }
                if (c < 8) {
                    *(float4*)(nb + (k4a * 16 + bls) * 4) = n0;
                    *(float4*)(nb + (k4b * 16 + bls) * 4) = n1;
                }
                __syncthreads();
            }

            const float psp = __fadd_rn(a, b3s[ol]);
            lif_update(psp, cur3, volt3, spk3);
        }
        // stage spikes, build + publish 16-bit mask slice (pb1 is free here)
        pb1[tid] = spk3;
        __syncthreads();
        if (tid < 16) {
            unsigned m = 0;
#pragma unroll
            for (int o = 0; o < 16; ++o)
                m |= (pb1[o * 16 + tid] > 0.5f ? 1u : 0u) << o;
            g_m3[(((t % 3) * 64) + bg * 16 + tid) * 16 + og] = (unsigned short)m;
        }
        gridbar_g(bg, 16);   // -------- bar 1 --------

        // ========== fc2 for step t-1 (og<2, ol==0) ==========
        if (og < 2 && ol == 0 && t >= 1) {
            const uint4 mv = *(const uint4*)&g_msf[((((t - 1) & 1) * 64) + b) * 8];
            unsigned M4[4] = {mv.x, mv.y, mv.z, mv.w};
            const float* rp0 = f2s + og * 128;
            float d = 0.f, pend = 0.f; int havep = 0;
#pragma unroll
            for (int w = 0; w < 4; ++w) {
                unsigned m = M4[w];
                const float* rp = rp0 + w * 32;
                while (m) {
                    int i = __ffs(m) - 1; m &= m - 1;
                    float nv = rp[i];
                    if (havep) d = __fadd_rn(d, pend);
                    pend = nv; havep = 1;
                }
            }
            if (havep) d = __fadd_rn(d, pend);
            outacc = __fadd_rn(outacc, __fmul_rn(d, tsws[t - 1]));
        }

        // ========== tc (3 taps) + rec: combined sparse 4-chain loop ==========
        {
            unsigned a0[8], a1[8], a2[8], ar[8];
            {
                const uint4* p0 = (const uint4*)&g_m3[(((t % 3) * 64) + b) * 16];
                uint4 u = p0[0], v = p0[1];
                a0[0]=u.x; a0[1]=u.y; a0[2]=u.z; a0[3]=u.w;
                a0[4]=v.x; a0[5]=v.y; a0[6]=v.z; a0[7]=v.w;
            }
            if (t >= 1) {
                const uint4* p1 = (const uint4*)&g_m3[((((t + 2) % 3) * 64) + b) * 16];
                uint4 u = p1[0], v = p1[1];
                a1[0]=u.x; a1[1]=u.y; a1[2]=u.z; a1[3]=u.w;
                a1[4]=v.x; a1[5]=v.y; a1[6]=v.z; a1[7]=v.w;
            } else {
#pragma unroll
                for (int w = 0; w < 8; ++w) a1[w] = 0u;
            }
            if (t >= 2) {
                const uint4* p2 = (const uint4*)&g_m3[((((t + 1) % 3) * 64) + b) * 16];
                uint4 u = p2[0], v = p2[1];
                a2[0]=u.x; a2[1]=u.y; a2[2]=u.z; a2[3]=u.w;
                a2[4]=v.x; a2[5]=v.y; a2[6]=v.z; a2[7]=v.w;
            } else {
#pragma unroll
                for (int w = 0; w < 8; ++w) a2[w] = 0u;
            }
            if (t >= 1) {
                const uint4* pr = (const uint4*)&g_mr[((((t & 1) ^ 1) * 64) + b) * 16];
                uint4 u = pr[0], v = pr[1];
                ar[0]=u.x; ar[1]=u.y; ar[2]=u.z; ar[3]=u.w;
                ar[4]=v.x; ar[5]=v.y; ar[6]=v.z; ar[7]=v.w;
            } else {
#pragma unroll
                for (int w = 0; w < 8; ++w) ar[w] = 0u;
            }

            const float* r0 = tcws + (0 * 16 + ol) * 264;
            const float* r1 = tcws + (1 * 16 + ol) * 264;
            const float* r2 = tcws + (2 * 16 + ol) * 264;
            const float* rr = recws + ol * 264;

            float d0 = 0.f, d1 = 0.f, d2 = 0.f, dr = 0.f;
#pragma unroll
            for (int w = 0; w < 8; ++w) {
                unsigned m0 = a0[w], m1 = a1[w], m2 = a2[w], mrr = ar[w];
                const float* q0 = r0 + w * 32;
                const float* q1 = r1 + w * 32;
                const float* q2 = r2 + w * 32;
                const float* qr = rr + w * 32;
                while (m0 | m1 | m2 | mrr) {
                    if (m0) { int i = __ffs(m0) - 1; m0 &= m0 - 1; d0 = __fadd_rn(d0, q0[i]); }
                    if (m1) { int i = __ffs(m1) - 1; m1 &= m1 - 1; d1 = __fadd_rn(d1, q1[i]); }
                    if (m2) { int i = __ffs(m2) - 1; m2 &= m2 - 1; d2 = __fadd_rn(d2, q2[i]); }
                    if (mrr){ int i = __ffs(mrr) - 1; mrr &= mrr - 1; dr = __fadd_rn(dr, qr[i]); }
                }
            }

            float a = 0.f;
            a = __fadd_rn(a, __fadd_rn(d0, tcbs[0 * 16 + ol]));
            if (t >= 1) a = __fadd_rn(a, __fadd_rn(d1, tcbs[1 * 16 + ol]));
            if (t >= 2) a = __fadd_rn(a, __fadd_rn(d2, tcbs[2 * 16 + ol]));
            lif_update(a, curt, voltt, spkt);

            const float pr = __fadd_rn(__fadd_rn(spkt, dr), recbs[ol]);
            lif_update(pr, curr, voltr, spkr);
        }
        // publish recurrent spike masks
        pb1[tid] = spkr;
        __syncthreads();
        if (tid < 16) {
            unsigned m = 0;
#pragma unroll
            for (int o = 0; o < 16; ++o)
                m |= (pb1[o * 16 + tid] > 0.5f ? 1u : 0u) << o;
            g_mr[(((t & 1) * 64) + bg * 16 + tid) * 16 + og] = (unsigned short)m;
        }
        gridbar_g(bg, 16);   // -------- bar 2 --------

        // ========== fc1 + LIF (og < 8), sparse pipelined chain ==========
        if (og < 8) {
            unsigned M8[8];
            {
                const uint4* p = (const uint4*)&g_mr[(((t & 1) * 64) + b) * 16];
                uint4 u = p[0], v = p[1];
                M8[0]=u.x; M8[1]=u.y; M8[2]=u.z; M8[3]=u.w;
                M8[4]=v.x; M8[5]=v.y; M8[6]=v.z; M8[7]=v.w;
            }
            const float* row = f1ws + ol * 264;
            float d = 0.f, pend = 0.f; int havep = 0;
#pragma unroll
            for (int w = 0; w < 8; ++w) {
                unsigned m = M8[w];
                const float* rp = row + w * 32;
                while (m) {
                    int i = __ffs(m) - 1; m &= m - 1;
                    float nv = rp[i];
                    if (havep) d = __fadd_rn(d, pend);
                    pend = nv; havep = 1;
                }
            }
            if (havep) d = __fadd_rn(d, pend);
            const float psp = __fadd_rn(d, f1bs[ol]);
            lif_update(psp, curf, voltf, spkf);
            pb1[tid] = spkf;
        }
        __syncthreads();
        if (og < 8 && tid < 16) {
            unsigned m = 0;
#pragma unroll
            for (int o = 0; o < 16; ++o)
                m |= (pb1[o * 16 + tid] > 0.5f ? 1u : 0u) << o;
            g_msf[(((t & 1) * 64) + bg * 16 + tid) * 8 + og] = (unsigned short)m;
        }
        // (no bar 3: fc2(t) runs after bar1 of step t+1, which orders fc1 writes)
    }

    gridbar_g(bg, 16);   // final: order fc1(199) mask writes
    if (og < 2 && ol == 0) {
        const uint4 mv = *(const uint4*)&g_msf[((((T_STEPS - 1) & 1) * 64) + b) * 8];
        unsigned M4[4] = {mv.x, mv.y, mv.z, mv.w};
        const float* rp0 = f2s + og * 128;
        float d = 0.f, pend = 0.f; int havep = 0;
#pragma unroll
        for (int w = 0; w < 4; ++w) {
            unsigned m = M4[w];
            const float* rp = rp0 + w * 32;
            while (m) {
                int i = __ffs(m) - 1; m &= m - 1;
                float nv = rp[i];
                if (havep) d = __fadd_rn(d, pend);
                pend = nv; havep = 1;
            }
        }
        if (havep) d = __fadd_rn(d, pend);
        outacc = __fadd_rn(outacc, __fmul_rn(d, tsws[T_STEPS - 1]));
        out[b * 2 + og] = outacc;
    }
}

// ============================================================================
extern "C" void kernel_launch(void* const* d_in, const int* in_sizes, int n_in,
                              void* d_out, int out_size)
{
    (void)in_sizes; (void)n_in; (void)out_size;
    const float* input = (const float*)d_in[0];
    const float* w1   = (const float*)d_in[1];
    const float* b1   = (const float*)d_in[2];
    const float* w2   = (const float*)d_in[3];
    const float* b2   = (const float*)d_in[4];
    const float* w3   = (const float*)d_in[5];
    const float* b3   = (const float*)d_in[6];
    const float* tcw  = (const float*)d_in[7];
    const float* tcb  = (const float*)d_in[8];
    const float* recw = (const float*)d_in[9];
    const float* recb = (const float*)d_in[10];
    const float* f1w  = (const float*)d_in[11];
    const float* f1b  = (const float*)d_in[12];
    const float* f2w  = (const float*)d_in[13];
    const float* tsw  = (const float*)d_in[14];
    float* out = (float*)d_out;

    cudaFuncSetAttribute(phaseA_kernel, cudaFuncAttributeMaxDynamicSharedMemorySize,
                         A_TOT * sizeof(float));
    cudaFuncSetAttribute(phaseB_kernel, cudaFuncAttributeMaxDynamicSharedMemorySize,
                         B_TOT * sizeof(float));

    phaseA_kernel<<<128, 128, A_TOT * sizeof(float)>>>(input, w1, b1, w2, b2);
    phaseB_kernel<<<64, 256, B_TOT * sizeof(float)>>>(w3, b3, tcw, tcb, recw, recb,
                                                      f1w, f1b, f2w, tsw, out);
}

// round 8
// speedup vs baseline: 1.4635x; 1.4611x over previous
#include <cuda_runtime.h>
#include <cstdint>
#define T_STEPS 200
typedef unsigned long long u64t;

__device__ float g_p[(size_t)T_STEPS * 288 * 64 * 4];   // [t][k4][b][4]
__device__ float g_s3[3 * 64 * 64 * 4];                  // [slot][k4][b][4]
__device__ float g_sr[2 * 64 * 256];                     // [buf][b][oc]
__device__ float g_sf[2 * 64 * 128];                     // [buf][b][row]
__device__ unsigned g_cnt[4 * 32];
__device__ volatile unsigned g_gen[4 * 32];

__device__ __forceinline__ void gridbar_g(int grp, unsigned n) {
    __syncthreads();
    if (threadIdx.x == 0) {
        unsigned* cnt = &g_cnt[grp * 32];
        volatile unsigned* gen = &g_gen[grp * 32];
        unsigned g = *gen;
        __threadfence();
        if (atomicAdd(cnt, 1u) == n - 1u) { *cnt = 0; __threadfence(); *gen = g + 1u; }
        else { while (*gen == g) { } }
        __threadfence();
    }
    __syncthreads();
}
__device__ __forceinline__ u64t pk2(float lo, float hi) {
    u64t r; asm("mov.b64 %0, {%1, %2};" : "=l"(r) : "f"(lo), "f"(hi)); return r;
}
__device__ __forceinline__ void upk2(u64t v, float& lo, float& hi) {
    asm("mov.b64 {%0, %1}, %2;" : "=f"(lo), "=f"(hi) : "l"(v));
}
__device__ __forceinline__ u64t fma2(u64t a, u64t b, u64t c) {
    u64t d; asm("fma.rn.f32x2 %0, %1, %2, %3;" : "=l"(d) : "l"(a), "l"(b), "l"(c)); return d;
}
__device__ __forceinline__ void lif_update(float psp, float& cur, float& volt, float& spk) {
    cur  = __fadd_rn(__fmul_rn(0.5f, cur), psp);
    volt = __fadd_rn(__fmul_rn(__fmul_rn(0.75f, volt), __fadd_rn(1.f, -spk)), cur);
    spk  = (volt > 0.5f) ? 1.f : 0.f;
}

// ================= Phase A (unchanged from R5) =================
#define A_XS 0
#define A_W1S 100
#define A_B1S 676
#define A_B2S 740
#define A_S1S 804
#define A_S2S 4964
#define A_W2P 7268
#define A_TOT 44132
__global__ __launch_bounds__(128, 1)
void phaseA_kernel(const float* __restrict__ input,
                   const float* __restrict__ w1, const float* __restrict__ b1,
                   const float* __restrict__ w2, const float* __restrict__ b2)
{
    extern __shared__ float sm[];
    float* xs = sm + A_XS; float* w1s = sm + A_W1S; float* b1s = sm + A_B1S;
    float* b2s = sm + A_B2S; float* s1s = sm + A_S1S; float* s2s = sm + A_S2S;
    float* w2p = sm + A_W2P;
    const int tid = threadIdx.x;
    const int b = blockIdx.x >> 1, h = blockIdx.x & 1;
    for (int i = tid; i < 36864; i += 128) {
        int oc = i / 576, r = i - oc * 576;
        w2p[(r * 32 + (oc >> 1)) * 2 + (oc & 1)] = w2[h * 36864 + i];
    }
    for (int i = tid; i < 576; i += 128) w1s[i] = w1[i];
    if (tid < 64) { b1s[tid] = b1[tid]; b2s[tid] = b2[h * 64 + tid]; }
    for (int i = tid; i < 4160; i += 128) s1s[i] = 0.f;
    for (int i = tid; i < 2304; i += 128) s2s[i] = 0.f;
    __syncthreads();
    const int p = tid >> 2, q = tid & 3;
    const int qy = q >> 1, qx = q & 1;
    const int y0a = qy * 4, x0a = qx * 4, y0b = qy * 3, x0b = qx * 3;
    float c1[2][16], v1[2][16], c2[2][9], v2[2][9], sp2[2][9];
#pragma unroll
    for (int o = 0; o < 2; ++o) {
#pragma unroll
        for (int i = 0; i < 16; ++i) { c1[o][i] = 0.f; v1[o][i] = 0.f; }
#pragma unroll
        for (int i = 0; i < 9; ++i) { c2[o][i] = 0.f; v2[o][i] = 0.f; sp2[o][i] = 0.f; }
    }
    const float* xin = input + (size_t)b * 20000;
    for (int t = 0; t < T_STEPS; ++t) {
        if (tid < 100) xs[tid] = xin[tid * 200 + t];
        __syncthreads();
#pragma unroll
        for (int o = 0; o < 2; ++o) {
            const int occ = 2 * p + o;
            const float bb = b1s[occ];
            const float* wv = w1s + occ * 9;
#pragma unroll
            for (int iy = 0; iy < 4; ++iy)
#pragma unroll
                for (int ix = 0; ix < 4; ++ix) {
                    const int y = y0a + iy, x = x0a + ix;
                    float a = 0.f;
#pragma unroll
                    for (int ky = 0; ky < 3; ++ky)
#pragma unroll
                        for (int kx = 0; kx < 3; ++kx)
                            a = __fmaf_rn(xs[(y + ky) * 10 + (x + kx)], wv[ky * 3 + kx], a);
                    const float psp = __fadd_rn(a, bb);
                    const int i = iy * 4 + ix, sidx = occ * 65 + y * 8 + x;
                    float sp = s1s[sidx];
                    lif_update(psp, c1[o][i], v1[o][i], sp);
                    s1s[sidx] = sp;
                }
        }
        __syncthreads();
        {
            u64t acc[9];
#pragma unroll
            for (int j = 0; j < 9; ++j) acc[j] = 0ull;
#pragma unroll 2
            for (int ic = 0; ic < 64; ++ic) {
                u64t ins[5][5];
#pragma unroll
                for (int r = 0; r < 5; ++r)
#pragma unroll
                    for (int c = 0; c < 5; ++c) {
                        float v = s1s[ic * 65 + (y0b + r) * 8 + (x0b + c)];
                        ins[r][c] = pk2(v, v);
                    }
#pragma unroll
                for (int kk = 0; kk < 9; ++kk) {
                    const int ky = kk / 3, kx = kk % 3;
                    const u64t w = *(const u64t*)(w2p + ((ic * 9 + kk) * 32 + p) * 2);
#pragma unroll
                    for (int dy = 0; dy < 3; ++dy)
#pragma unroll
                        for (int dx = 0; dx < 3; ++dx)
                            acc[dy * 3 + dx] = fma2(ins[dy + ky][dx + kx], w, acc[dy * 3 + dx]);
                }
            }
#pragma unroll
            for (int j = 0; j < 9; ++j) {
                const int dy = j / 3, dx = j % 3;
                float alo, ahi; upk2(acc[j], alo, ahi);
#pragma unroll
                for (int o = 0; o < 2; ++o) {
                    const int occ = 2 * p + o;
                    const float psp = __fadd_rn(o ? ahi : alo, b2s[occ]);
                    lif_update(psp, c2[o][j], v2[o][j], sp2[o][j]);
                    s2s[occ * 36 + (y0b + dy) * 6 + (x0b + dx)] = sp2[o][j];
                }
            }
        }
        __syncthreads();
        for (int idx = tid; idx < 576; idx += 128) {
            int c = idx / 9, pos = idx - c * 9;
            int py = pos / 3, px = pos - py * 3;
            float v = 0.25f * ((s2s[c * 36 + (2 * py) * 6 + 2 * px]
                              + s2s[c * 36 + (2 * py) * 6 + 2 * px + 1])
                             + (s2s[c * 36 + (2 * py + 1) * 6 + 2 * px]
                              + s2s[c * 36 + (2 * py + 1) * 6 + 2 * px + 1]));
            int k = (h * 64 + c) * 9 + pos;
            g_p[(size_t)t * 73728 + (size_t)(k >> 2) * 256 + b * 4 + (k & 3)] = v;
        }
    }
}

// ================= Phase B =================
#define B_W3P  0        // 8*2304 = 18432  [pair][k][2]
#define B_TCW  18432    // 12672
#define B_RECW 31104    // 4224
#define B_F1W  35328    // 4224
#define B_B3   39552    // 16
#define B_TCB  39568    // 48
#define B_RECB 39616    // 16
#define B_F1B  39632    // 16
#define B_F2S  39648    // 256
#define B_TSW  39904    // 208
#define B_S3C  40112    // 3*4096
#define B_PBUF 52400    // 2*2048
#define B_TOT  56496

// serial dot over contiguous k=256 row (global, L2), ping-pong prefetch
__device__ __forceinline__ float dot256g(const float* __restrict__ wr,
                                         const float* __restrict__ xr) {
    float4 x[16];
#pragma unroll
    for (int j = 0; j < 8; ++j) x[j] = __ldcg((const float4*)(xr + j * 4));
    float a = 0.f;
#pragma unroll
    for (int g = 0; g < 8; ++g) {
        const int cb = (g & 1) * 8, nb = ((g + 1) & 1) * 8;
        if (g < 7) {
#pragma unroll
            for (int j = 0; j < 8; ++j)
                x[nb + j] = __ldcg((const float4*)(xr + ((g + 1) * 8 + j) * 4));
        }
#pragma unroll
        for (int j = 0; j < 8; ++j) {
            float4 w = *(const float4*)(wr + (g * 8 + j) * 4);
            a = __fmaf_rn(w.x, x[cb + j].x, a);
            a = __fmaf_rn(w.y, x[cb + j].y, a);
            a = __fmaf_rn(w.z, x[cb + j].z, a);
            a = __fmaf_rn(w.w, x[cb + j].w, a);
        }
    }
    return a;
}
__device__ __forceinline__ float dot128g(const float* __restrict__ wr,
                                         const float* __restrict__ xr) {
    float4 x[32];
#pragma unroll
    for (int j = 0; j < 32; ++j) x[j] = __ldcg((const float4*)(xr + j * 4));
    float a = 0.f;
#pragma unroll
    for (int j = 0; j < 32; ++j) {
        float4 w = *(const float4*)(wr + j * 4);
        a = __fmaf_rn(w.x, x[j].x, a);
        a = __fmaf_rn(w.y, x[j].y, a);
        a = __fmaf_rn(w.z, x[j].z, a);
        a = __fmaf_rn(w.w, x[j].w, a);
    }
    return a;
}

__global__ __launch_bounds__(256, 1)
void phaseB_kernel(const float* __restrict__ w3, const float* __restrict__ b3,
                   const float* __restrict__ tcw, const float* __restrict__ tcb,
                   const float* __restrict__ recw, const float* __restrict__ recb,
                   const float* __restrict__ f1w, const float* __restrict__ f1b,
                   const float* __restrict__ f2w, const float* __restrict__ tsw,
                   float* __restrict__ out)
{
    extern __shared__ float sm[];
    float* w3p = sm + B_W3P; float* tcws = sm + B_TCW; float* recws = sm + B_RECW;
    float* f1ws = sm + B_F1W; float* b3s = sm + B_B3; float* tcbs = sm + B_TCB;
    float* recbs = sm + B_RECB; float* f1bs = sm + B_F1B; float* f2s = sm + B_F2S;
    float* tsws = sm + B_TSW; float* s3c = sm + B_S3C; float* pb = sm + B_PBUF;

    const int tid = threadIdx.x;
    const int og = blockIdx.x >> 2, bg = blockIdx.x & 3;
    const int ol = tid >> 4, bl = tid & 15;
    const int b = bg * 16 + bl;
    const int cp = tid >> 4;           // consumer pair 0..7 (tid<128)
    const bool cons = (tid < 128);

    for (int g = tid; g < 18432; g += 256) {
        int op = g / 2304, r = g - op * 2304, k = r >> 1, l = r & 1;
        w3p[g] = w3[(size_t)(og * 16 + op * 2 + l) * 1152 + k];
    }
    for (int g = tid; g < 3 * 16 * 256; g += 256) {
        int i = g >> 12, r = g & 4095, o = r >> 8, k = r & 255;
        tcws[(i * 16 + o) * 264 + k] = tcw[i * 65536 + (og * 16 + o) * 256 + k];
    }
    for (int g = tid; g < 4096; g += 256) {
        int o = g >> 8, k = g & 255;
        recws[o * 264 + k] = recw[(og * 16 + o) * 256 + k];
        if (og < 8) f1ws[o * 264 + k] = f1w[(og * 16 + o) * 256 + k];
    }
    if (tid < 16) {
        b3s[tid] = b3[og * 16 + tid];
        recbs[tid] = recb[og * 16 + tid];
        if (og < 8) f1bs[tid] = f1b[og * 16 + tid];
    }
    if (tid < 48) tcbs[tid] = tcb[(tid >> 4) * 256 + og * 16 + (tid & 15)];
    f2s[tid] = f2w[tid];
    for (int g = tid; g < 200; g += 256) tsws[g] = tsw[g];
    __syncthreads();

    float cur3a = 0.f, volt3a = 0.f, spk3a = 0.f;
    float cur3b = 0.f, volt3b = 0.f, spk3b = 0.f;
    float curt = 0.f, voltt = 0.f, spkt = 0.f;
    float curr = 0.f, voltr = 0.f, spkr = 0.f;
    float curf = 0.f, voltf = 0.f, spkf = 0.f;
    float outacc = 0.f;

    for (int t = 0; t < T_STEPS; ++t) {
        // ---- conv3: producers stage chunks, consumers run FMA2 chains ----
        {
            const float* tb = g_p + (size_t)t * 73728;
            if (!cons) {
                const int pid = tid - 128;
#pragma unroll
                for (int j = 0; j < 4; ++j) {
                    int i = pid * 4 + j, k4 = i >> 4, b2 = i & 15;
                    float4 v = __ldcg((const float4*)(tb + (size_t)k4 * 256 + (bg * 16 + b2) * 4));
                    *(float4*)(pb + (k4 * 16 + b2) * 4) = v;
                }
            }
            __syncthreads();
            u64t acc = 0ull;
            for (int c = 0; c < 9; ++c) {
                if (cons) {
                    const float* xb = pb + (c & 1) * 2048;
                    const u64t* wb = (const u64t*)(w3p + cp * 2304 + c * 256);
#pragma unroll
                    for (int k4 = 0; k4 < 32; ++k4) {
                        float4 x = *(const float4*)(xb + (k4 * 16 + bl) * 4);
                        const u64t* w = wb + k4 * 4;
                        acc = fma2(pk2(x.x, x.x), w[0], acc);
                        acc = fma2(pk2(x.y, x.y), w[1], acc);
                        acc = fma2(pk2(x.z, x.z), w[2], acc);
                        acc = fma2(pk2(x.w, x.w), w[3], acc);
                    }
                } else if (c + 1 < 9) {
                    const int pid = tid - 128, bs = (c + 1) & 1;
#pragma unroll
                    for (int j = 0; j < 4; ++j) {
                        int i = pid * 4 + j, k4 = i >> 4, b2 = i & 15;
                        float4 v = __ldcg((const float4*)(tb + (size_t)((c + 1) * 32 + k4) * 256
                                                         + (bg * 16 + b2) * 4));
                        *(float4*)(pb + bs * 2048 + (k4 * 16 + b2) * 4) = v;
                    }
                }
                __syncthreads();
            }
            if (cons) {
                float alo, ahi; upk2(acc, alo, ahi);
                lif_update(__fadd_rn(alo, b3s[2 * cp]),     cur3a, volt3a, spk3a);
                lif_update(__fadd_rn(ahi, b3s[2 * cp + 1]), cur3b, volt3b, spk3b);
                float2 s2v; s2v.x = spk3a; s2v.y = spk3b;
                *(float2*)&g_s3[((t % 3) * 64 + og * 4 + (cp >> 1)) * 256 + b * 4 + 2 * (cp & 1)] = s2v;
            }
        }
        gridbar_g(bg, 16);   // ---- bar 1 ----

        // ---- stage fresh s3 slot into SMEM cache ----
        {
            const int slot = t % 3;
#pragma unroll
            for (int j = 0; j < 4; ++j) {
                int i = tid + j * 256, k4 = i >> 4, b2 = i & 15;
                float4 v = __ldcg((const float4*)(g_s3 + (slot * 64 + k4) * 256 + (bg * 16 + b2) * 4));
                *(float4*)(s3c + slot * 4096 + (k4 * 16 + b2) * 4) = v;
            }
        }
        __syncthreads();

        // ---- tc (SMEM) + rec (global contiguous) ----
        {
            const float* x0 = s3c + (t % 3) * 4096 + bl * 4;
            const float* x1 = s3c + ((t + 2) % 3) * 4096 + bl * 4;
            const float* x2 = s3c + ((t + 1) % 3) * 4096 + bl * 4;
            const float* w0 = tcws + (0 * 16 + ol) * 264;
            const float* w1v = tcws + (1 * 16 + ol) * 264;
            const float* w2v = tcws + (2 * 16 + ol) * 264;
            const bool h1 = (t >= 1), h2 = (t >= 2);
            float d0 = 0.f, d1 = 0.f, d2 = 0.f;
#pragma unroll 8
            for (int k4 = 0; k4 < 64; ++k4) {
                float4 a0 = *(const float4*)(x0 + k4 * 64);
                float4 q0 = *(const float4*)(w0 + k4 * 4);
                d0 = __fmaf_rn(q0.x, a0.x, d0); d0 = __fmaf_rn(q0.y, a0.y, d0);
                d0 = __fmaf_rn(q0.z, a0.z, d0); d0 = __fmaf_rn(q0.w, a0.w, d0);
                if (h1) {
                    float4 a1 = *(const float4*)(x1 + k4 * 64);
                    float4 q1 = *(const float4*)(w1v + k4 * 4);
                    d1 = __fmaf_rn(q1.x, a1.x, d1); d1 = __fmaf_rn(q1.y, a1.y, d1);
                    d1 = __fmaf_rn(q1.z, a1.z, d1); d1 = __fmaf_rn(q1.w, a1.w, d1);
                }
                if (h2) {
                    float4 a2 = *(const float4*)(x2 + k4 * 64);
                    float4 q2 = *(const float4*)(w2v + k4 * 4);
                    d2 = __fmaf_rn(q2.x, a2.x, d2); d2 = __fmaf_rn(q2.y, a2.y, d2);
                    d2 = __fmaf_rn(q2.z, a2.z, d2); d2 = __fmaf_rn(q2.w, a2.w, d2);
                }
            }
            float a = __fadd_rn(0.f, __fadd_rn(d0, tcbs[ol]));
            if (h1) a = __fadd_rn(a, __fadd_rn(d1, tcbs[16 + ol]));
            if (h2) a = __fadd_rn(a, __fadd_rn(d2, tcbs[32 + ol]));
            lif_update(a, curt, voltt, spkt);

            float dotr = 0.f;
            if (t > 0)
                dotr = dot256g(recws + ol * 264, g_sr + ((t & 1) ^ 1) * 16384 + b * 256);
            const float pr = __fadd_rn(__fadd_rn(spkt, dotr), recbs[ol]);
            lif_update(pr, curr, voltr, spkr);
            g_sr[(t & 1) * 16384 + b * 256 + og * 16 + ol] = spkr;
        }
        gridbar_g(bg, 16);   // ---- bar 2 ----

        // ---- fc1 (og<8) ; fc2(t-1) in og15 ----
        if (og < 8) {
            const float d = dot256g(f1ws + ol * 264, g_sr + (t & 1) * 16384 + b * 256);
            lif_update(__fadd_rn(d, f1bs[ol]), curf, voltf, spkf);
            g_sf[(t & 1) * 8192 + b * 128 + og * 16 + ol] = spkf;
        } else if (og == 15 && tid < 32 && t >= 1) {
            const int o = tid >> 4, bb = bg * 16 + (tid & 15);
            const float d = dot128g(f2s + o * 128, g_sf + ((t - 1) & 1) * 8192 + bb * 128);
            outacc = __fadd_rn(outacc, __fmul_rn(d, tsws[t - 1]));
        }
    }

    gridbar_g(bg, 16);
    if (og == 15 && tid < 32) {
        const int o = tid >> 4, bb = bg * 16 + (tid & 15);
        const float d = dot128g(f2s + o * 128, g_sf + ((T_STEPS - 1) & 1) * 8192 + bb * 128);
        outacc = __fadd_rn(outacc, __fmul_rn(d, tsws[T_STEPS - 1]));
        out[bb * 2 + o] = outacc;
    }
}

extern "C" void kernel_launch(void* const* d_in, const int* in_sizes, int n_in,
                              void* d_out, int out_size)
{
    (void)in_sizes; (void)n_in; (void)out_size;
    const float* input = (const float*)d_in[0];
    const float* w1 = (const float*)d_in[1];
    const float* b1 = (const float*)d_in[2];
    const float* w2 = (const float*)d_in[3];
    const float* b2 = (const float*)d_in[4];
    const float* w3 = (const float*)d_in[5];
    const float* b3 = (const float*)d_in[6];
    const float* tcw = (const float*)d_in[7];
    const float* tcb = (const float*)d_in[8];
    const float* recw = (const float*)d_in[9];
    const float* recb = (const float*)d_in[10];
    const float* f1w = (const float*)d_in[11];
    const float* f1b = (const float*)d_in[12];
    const float* f2w = (const float*)d_in[13];
    const float* tsw = (const float*)d_in[14];
    float* out = (float*)d_out;

    cudaFuncSetAttribute(phaseA_kernel, cudaFuncAttributeMaxDynamicSharedMemorySize,
                         A_TOT * sizeof(float));
    cudaFuncSetAttribute(phaseB_kernel, cudaFuncAttributeMaxDynamicSharedMemorySize,
                         B_TOT * sizeof(float));
    phaseA_kernel<<<128, 128, A_TOT * sizeof(float)>>>(input, w1, b1, w2, b2);
    phaseB_kernel<<<64, 256, B_TOT * sizeof(float)>>>(w3, b3, tcw, tcb, recw, recb,
                                                      f1w, f1b, f2w, tsw, out);
}